// round 15
// baseline (speedup 1.0000x reference)
#include <cuda_runtime.h>
#include <cuda_bf16.h>

#define TOKENS 2048
#define DDIM   1024
#define PDIM   32
#define NPAT   256
#define TOPK   4
#define NPAIRS (TOKENS * TOPK)            // 8192
#define CHUNK  32
#define MAXCHUNKS (NPAIRS / CHUNK + NPAT) // 512
#define WPAD   36     // Vd/proj row stride (floats)
#define XPAD   68     // x / Vu slice row stride (floats)
#define BUFSZ  4480   // per-stage buffer: Vd[64][36]=2304 + x[32][68]=2176
#define NBUF   2
#define NSTAGE 32     // 16 A-stages + 16 B-stages (64 d each)

// ---------------- global scratch (static, allocation-free) ----------------
__device__ int   g_eidx[NPAIRS];
__device__ float g_wt[NPAIRS];
__device__ int   g_list[NPAIRS];
__device__ int   g_tiles[MAXCHUNKS];
__device__ int   g_nchunks;
__device__ float g_hwT[DDIM * PDIM];
__device__ float g_keysT[PDIM * NPAT];
__device__ unsigned int g_poutb[NPAIRS * DDIM / 2];       // bf16x2

__device__ __forceinline__ float my_silu(float z) {
    return z / (1.0f + __expf(-z));
}

__device__ __forceinline__ void mma_tf32(float& c0, float& c1, float& c2, float& c3,
                                         unsigned int a0, unsigned int a1,
                                         unsigned int a2, unsigned int a3,
                                         unsigned int b0, unsigned int b1) {
    asm volatile(
        "mma.sync.aligned.m16n8k8.row.col.f32.tf32.tf32.f32 "
        "{%0,%1,%2,%3}, {%4,%5,%6,%7}, {%8,%9}, {%0,%1,%2,%3};"
        : "+f"(c0), "+f"(c1), "+f"(c2), "+f"(c3)
        : "r"(a0), "r"(a1), "r"(a2), "r"(a3), "r"(b0), "r"(b1));
}

__device__ __forceinline__ void cp_async16(unsigned int dst, const void* src) {
    asm volatile("cp.async.cg.shared.global [%0], [%1], 16;" :: "r"(dst), "l"(src));
}
__device__ __forceinline__ void cp_commit() {
    asm volatile("cp.async.commit_group;");
}
template<int N> __device__ __forceinline__ void cp_wait() {
    asm volatile("cp.async.wait_group %0;" :: "n"(N));
}

// ---------------- kernel 0: transpose hasher_w and keys ----------------
__global__ void prep_kernel(const float* __restrict__ hw,
                            const float* __restrict__ keys)
{
    const int tid = blockIdx.x * 256 + threadIdx.x;
    if (tid < (PDIM * DDIM) / 4) {
        const int p = tid >> 8;
        const float4 v = ((const float4*)hw)[tid];
        const int d = (tid & 255) * 4;
        g_hwT[(d + 0) * PDIM + p] = v.x;
        g_hwT[(d + 1) * PDIM + p] = v.y;
        g_hwT[(d + 2) * PDIM + p] = v.z;
        g_hwT[(d + 3) * PDIM + p] = v.w;
    }
    if (tid < (NPAT * PDIM) / 4) {
        const int n = tid >> 3;
        const int q = tid & 7;
        const float4 v = ((const float4*)keys)[tid];
        g_keysT[(q * 4 + 0) * NPAT + n] = v.x;
        g_keysT[(q * 4 + 1) * NPAT + n] = v.y;
        g_keysT[(q * 4 + 2) * NPAT + n] = v.z;
        g_keysT[(q * 4 + 3) * NPAT + n] = v.w;
    }
}

// ---------------- kernel 1: routing — 8 tokens/block, 256 blocks ----------------
__global__ __launch_bounds__(256)
void routing_kernel(const float* __restrict__ x,
                    const float* __restrict__ scale)
{
    __shared__ float wS[256 * WPAD];
    __shared__ float shh[8][PDIM];

    const int tid  = threadIdx.x;
    const int warp = tid >> 5;
    const int lane = tid & 31;
    const int tok  = blockIdx.x * 8 + warp;

    const int p4 = lane & 7;
    const int dq = lane >> 3;

    float4 acc = make_float4(0.f, 0.f, 0.f, 0.f);
    const float* xr0 = x + (size_t)tok * DDIM;

    for (int slice = 0; slice < 4; slice++) {
        __syncthreads();
        {
            const float4* src = (const float4*)(g_hwT + slice * 256 * PDIM);
            #pragma unroll
            for (int k = 0; k < 8; k++) {
                const int i = tid + k * 256;
                const int r = i >> 3, q = i & 7;
                *(float4*)&wS[r * WPAD + q * 4] = src[i];
            }
        }
        __syncthreads();

        const float* xr = xr0 + slice * 256;
        #pragma unroll 2
        for (int db = 0; db < 256; db += 16) {
            const float4 xv = *(const float4*)(xr + db + dq * 4);
            const int wb = (db + dq * 4) * WPAD + p4 * 4;
            #pragma unroll
            for (int j = 0; j < 4; j++) {
                const float4 w = *(const float4*)&wS[wb + j * WPAD];
                const float s = (j==0)?xv.x:(j==1)?xv.y:(j==2)?xv.z:xv.w;
                acc.x += s*w.x; acc.y += s*w.y; acc.z += s*w.z; acc.w += s*w.w;
            }
        }
    }

    #pragma unroll
    for (int o = 8; o <= 16; o <<= 1) {
        acc.x += __shfl_xor_sync(0xFFFFFFFFu, acc.x, o);
        acc.y += __shfl_xor_sync(0xFFFFFFFFu, acc.y, o);
        acc.z += __shfl_xor_sync(0xFFFFFFFFu, acc.z, o);
        acc.w += __shfl_xor_sync(0xFFFFFFFFu, acc.w, o);
    }
    if (dq == 0) *(float4*)&shh[warp][p4 * 4] = acc;
    __syncthreads();

    {
        const float4* src = (const float4*)g_keysT;
        #pragma unroll
        for (int k = 0; k < 8; k++)
            ((float4*)wS)[tid + k * 256] = src[tid + k * 256];
    }
    __syncthreads();

    float v[8];
    #pragma unroll
    for (int j = 0; j < 8; j++) v[j] = 0.f;
    #pragma unroll 4
    for (int p = 0; p < PDIM; p++) {
        const float hp = shh[warp][p];
        const int kb = p * NPAT + lane;
        #pragma unroll
        for (int j = 0; j < 8; j++)
            v[j] += hp * wS[kb + 32 * j];
    }

    float wv[TOPK]; int widx[TOPK];
    #pragma unroll
    for (int k = 0; k < TOPK; k++) {
        float bv = v[0]; int bj = 0;
        #pragma unroll
        for (int j = 1; j < 8; j++)
            if (v[j] > bv) { bv = v[j]; bj = j; }
        int bidx = lane + 32 * bj;
        #pragma unroll
        for (int o = 16; o; o >>= 1) {
            float ov = __shfl_xor_sync(0xFFFFFFFFu, bv, o);
            int   oi = __shfl_xor_sync(0xFFFFFFFFu, bidx, o);
            if (ov > bv || (ov == bv && oi < bidx)) { bv = ov; bidx = oi; }
        }
        wv[k] = bv; widx[k] = bidx;
        if ((bidx & 31) == lane) v[bidx >> 5] = -1e30f;
    }

    if (lane == 0) {
        float m = wv[0];
        #pragma unroll
        for (int k = 1; k < TOPK; k++) m = fmaxf(m, wv[k]);
        float e[TOPK], s = 0.0f;
        #pragma unroll
        for (int k = 0; k < TOPK; k++) { e[k] = __expf(wv[k] - m); s += e[k]; }
        const float inv = scale[0] / s;
        #pragma unroll
        for (int k = 0; k < TOPK; k++) {
            const int pair = (tok << 2) | k;
            g_eidx[pair] = widx[k];
            g_wt[pair]   = e[k] * inv;
        }
    }
}

// ---------------- kernel 2: scheduler ----------------
__global__ __launch_bounds__(NPAT, 1)
void build_tiles_kernel()
{
    __shared__ int cnt[NPAT];
    __shared__ int scn[NPAT];
    __shared__ int base[NPAT];
    __shared__ int off[NPAT];

    const int t = threadIdx.x;
    cnt[t] = 0; off[t] = 0;
    __syncthreads();

    for (int i = t; i < NPAIRS; i += NPAT)
        atomicAdd(&cnt[g_eidx[i]], 1);
    __syncthreads();

    scn[t] = cnt[t];
    __syncthreads();
    for (int o = 1; o < NPAT; o <<= 1) {
        int add = (t >= o) ? scn[t - o] : 0;
        __syncthreads();
        scn[t] += add;
        __syncthreads();
    }
    base[t] = scn[t] - cnt[t];
    __syncthreads();

    for (int i = t; i < NPAIRS; i += NPAT) {
        const int e = g_eidx[i];
        const int slot = atomicAdd(&off[e], 1);
        g_list[base[e] + slot] = i;
    }

    const int nch = (cnt[t] + CHUNK - 1) / CHUNK;
    scn[t] = nch;
    __syncthreads();
    for (int o = 1; o < NPAT; o <<= 1) {
        int add = (t >= o) ? scn[t - o] : 0;
        __syncthreads();
        scn[t] += add;
        __syncthreads();
    }
    const int cbase = scn[t] - nch;
    for (int i = 0; i < nch; i++) {
        const int start = base[t] + i * CHUNK;
        const int c     = min(CHUNK, cnt[t] - i * CHUNK);
        g_tiles[cbase + i] = (t << 19) | (start << 6) | c;
    }
    if (t == NPAT - 1) g_nchunks = scn[t];
}

// ---------------- kernel 3: fused expert — 2-buffer pipeline, 40KB smem, 5 CTA/SM ----------------
// One block per chunk. 32 stages of 64 d: s<16 phase A (Vd+x), s>=16 phase B (Vu).
__global__ __launch_bounds__(256)
void expert_kernel(const float* __restrict__ x,
                   const float* __restrict__ vd,
                   const float* __restrict__ vu)
{
    extern __shared__ float sm[];
    float* projS = sm + NBUF * BUFSZ;
    __shared__ int   spair[CHUNK];
    __shared__ float wtS[CHUNK];

    const int chunkId = blockIdx.x;
    if (chunkId >= g_nchunks) return;

    const int te    = g_tiles[chunkId];
    const int e     = te >> 19;
    const int start = (te >> 6) & 0x1FFF;
    const int cnt   = te & 0x3F;

    const int tid = threadIdx.x;
    if (tid < CHUNK) {
        const int pr = g_list[start + min(tid, cnt - 1)];
        spair[tid] = pr;
        wtS[tid]   = g_wt[pr];
    }
    __syncthreads();

    const int warp = tid >> 5;
    const int lane = tid & 31;
    const int grp  = lane >> 2;
    const int t4   = lane & 3;
    const int mt   = warp & 1;       // m-tile (tokens 16*mt..)
    const int nt   = warp >> 1;      // phase-A n-tile / phase-B col group

    // unified stage issue: s<16 -> A (Vd 64x32 + x 32x64); s>=16 -> B (Vu 32x64)
    auto issue = [&](int s) {
        float* b = sm + (s & (NBUF - 1)) * BUFSZ;
        if (s < 16) {
            const unsigned int wb = (unsigned int)__cvta_generic_to_shared(b);
            const unsigned int xb = (unsigned int)__cvta_generic_to_shared(b + 2304);
            const float* wsrc = vd + ((size_t)e * DDIM + s * 64) * PDIM;
            #pragma unroll
            for (int k = 0; k < 2; k++) {
                const int i = tid + k * 256;          // 0..511
                const int r = i >> 3, q = i & 7;
                cp_async16(wb + (r * WPAD + q * 4) * 4, wsrc + r * PDIM + q * 4);
            }
            #pragma unroll
            for (int k = 0; k < 2; k++) {
                const int i = tid + k * 256;
                const int r = i >> 4, c = i & 15;
                const float* xsrc = x + (size_t)(spair[r] >> 2) * DDIM + s * 64 + c * 4;
                cp_async16(xb + (r * XPAD + c * 4) * 4, xsrc);
            }
        } else {
            const int s16 = s - 16;
            const unsigned int vb = (unsigned int)__cvta_generic_to_shared(b);
            const float* vsrc = vu + (size_t)e * PDIM * DDIM + s16 * 64;
            #pragma unroll
            for (int k = 0; k < 2; k++) {
                const int i = tid + k * 256;
                const int p = i >> 4, c = i & 15;
                cp_async16(vb + (p * XPAD + c * 4) * 4, vsrc + p * DDIM + c * 4);
            }
        }
    };

    // phase-A accumulators (even/odd k-step chains)
    float ce0 = 0.f, ce1 = 0.f, ce2 = 0.f, ce3 = 0.f;
    float co0 = 0.f, co1 = 0.f, co2 = 0.f, co3 = 0.f;

    issue(0); cp_commit();

    for (int s = 0; s < NSTAGE; s++) {
        if (s < NSTAGE - 1) { issue(s + 1); cp_commit(); cp_wait<1>(); }
        else                { cp_wait<0>(); }
        __syncthreads();

        float* b = sm + (s & (NBUF - 1)) * BUFSZ;

        if (s < 16) {
            // ---- phase A consume: 8 k-steps of 8 ----
            const float* xb = b + 2304;
            const int arow = (mt * 16 + grp) * XPAD + t4;
            #pragma unroll
            for (int kk = 0; kk < 8; kk += 2) {
                {
                    const int kb = kk * 8;
                    const unsigned int a0 = __float_as_uint(xb[arow + kb]);
                    const unsigned int a1 = __float_as_uint(xb[arow + 8 * XPAD + kb]);
                    const unsigned int a2 = __float_as_uint(xb[arow + kb + 4]);
                    const unsigned int a3 = __float_as_uint(xb[arow + 8 * XPAD + kb + 4]);
                    const unsigned int b0 = __float_as_uint(b[(kb + t4) * WPAD + nt * 8 + grp]);
                    const unsigned int b1 = __float_as_uint(b[(kb + t4 + 4) * WPAD + nt * 8 + grp]);
                    mma_tf32(ce0, ce1, ce2, ce3, a0, a1, a2, a3, b0, b1);
                }
                {
                    const int kb = kk * 8 + 8;
                    const unsigned int a0 = __float_as_uint(xb[arow + kb]);
                    const unsigned int a1 = __float_as_uint(xb[arow + 8 * XPAD + kb]);
                    const unsigned int a2 = __float_as_uint(xb[arow + kb + 4]);
                    const unsigned int a3 = __float_as_uint(xb[arow + 8 * XPAD + kb + 4]);
                    const unsigned int b0 = __float_as_uint(b[(kb + t4) * WPAD + nt * 8 + grp]);
                    const unsigned int b1 = __float_as_uint(b[(kb + t4 + 4) * WPAD + nt * 8 + grp]);
                    mma_tf32(co0, co1, co2, co3, a0, a1, a2, a3, b0, b1);
                }
            }
        } else {
            if (s == 16) {
                // silu + gate weight -> projS[32][36]
                const float c0 = ce0 + co0, c1 = ce1 + co1;
                const float c2 = ce2 + co2, c3 = ce3 + co3;
                const int row0 = mt * 16 + grp;
                const int col  = nt * 8 + t4 * 2;
                const float w0 = wtS[row0], w1 = wtS[row0 + 8];
                projS[row0 * WPAD + col]           = w0 * my_silu(c0);
                projS[row0 * WPAD + col + 1]       = w0 * my_silu(c1);
                projS[(row0 + 8) * WPAD + col]     = w1 * my_silu(c2);
                projS[(row0 + 8) * WPAD + col + 1] = w1 * my_silu(c3);
                __syncthreads();
            }

            // ---- phase B consume: 64-d slice, warp = (mt, 16-col group) ----
            const int s16 = s - 16;
            const int nb0 = nt * 16;
            float d0[4] = {0.f,0.f,0.f,0.f};
            float d1[4] = {0.f,0.f,0.f,0.f};
            const int arow = (mt * 16 + grp) * WPAD + t4;
            #pragma unroll
            for (int kk = 0; kk < 4; kk++) {
                const int kb = kk * 8;
                const unsigned int a0 = __float_as_uint(projS[arow + kb]);
                const unsigned int a1 = __float_as_uint(projS[arow + 8 * WPAD + kb]);
                const unsigned int a2 = __float_as_uint(projS[arow + kb + 4]);
                const unsigned int a3 = __float_as_uint(projS[arow + 8 * WPAD + kb + 4]);
                {
                    const unsigned int b0 = __float_as_uint(b[(kb + t4) * XPAD + nb0 + grp]);
                    const unsigned int b1 = __float_as_uint(b[(kb + t4 + 4) * XPAD + nb0 + grp]);
                    mma_tf32(d0[0], d0[1], d0[2], d0[3], a0, a1, a2, a3, b0, b1);
                }
                {
                    const unsigned int b0 = __float_as_uint(b[(kb + t4) * XPAD + nb0 + 8 + grp]);
                    const unsigned int b1 = __float_as_uint(b[(kb + t4 + 4) * XPAD + nb0 + 8 + grp]);
                    mma_tf32(d1[0], d1[1], d1[2], d1[3], a0, a1, a2, a3, b0, b1);
                }
            }

            const int tok0 = mt * 16 + grp;
            const int tok1 = tok0 + 8;
            const int colb = s16 * 64 + nb0 + t4 * 2;
            if (tok0 < cnt) {
                __nv_bfloat162 v0 = __floats2bfloat162_rn(d0[0], d0[1]);
                __nv_bfloat162 v1 = __floats2bfloat162_rn(d1[0], d1[1]);
                const int rb = spair[tok0] * DDIM;
                g_poutb[(rb + colb) >> 1]     = *(unsigned int*)&v0;
                g_poutb[(rb + colb + 8) >> 1] = *(unsigned int*)&v1;
            }
            if (tok1 < cnt) {
                __nv_bfloat162 v0 = __floats2bfloat162_rn(d0[2], d0[3]);
                __nv_bfloat162 v1 = __floats2bfloat162_rn(d1[2], d1[3]);
                const int rb = spair[tok1] * DDIM;
                g_poutb[(rb + colb) >> 1]     = *(unsigned int*)&v0;
                g_poutb[(rb + colb + 8) >> 1] = *(unsigned int*)&v1;
            }
        }
        __syncthreads();
    }
}

// ---------------- kernel 4: combine ----------------
__global__ __launch_bounds__(256)
void combine_kernel(const float* __restrict__ x, float* __restrict__ out)
{
    const int tok = blockIdx.x;
    const int t   = threadIdx.x;
    float4 o = ((const float4*)(x + (size_t)tok * DDIM))[t];
    #pragma unroll
    for (int k = 0; k < TOPK; k++) {
        const uint2 u = *(const uint2*)&g_poutb[((tok << 2) | k) * (DDIM / 2) + t * 2];
        const __nv_bfloat162 lo = *(const __nv_bfloat162*)&u.x;
        const __nv_bfloat162 hi = *(const __nv_bfloat162*)&u.y;
        const float2 flo = __bfloat1622float2(lo);
        const float2 fhi = __bfloat1622float2(hi);
        o.x += flo.x; o.y += flo.y; o.z += fhi.x; o.w += fhi.y;
    }
    ((float4*)(out + (size_t)tok * DDIM))[t] = o;
}

// ---------------- launch ----------------
extern "C" void kernel_launch(void* const* d_in, const int* in_sizes, int n_in,
                              void* d_out, int out_size) {
    const float* x     = (const float*)d_in[0];
    const float* hw    = (const float*)d_in[1];
    const float* keys  = (const float*)d_in[2];
    const float* vd    = (const float*)d_in[3];
    const float* vu    = (const float*)d_in[4];
    const float* scale = (const float*)d_in[5];
    float* out = (float*)d_out;

    const int smemE = (NBUF * BUFSZ + CHUNK * WPAD) * (int)sizeof(float);  // 40448 B
    cudaFuncSetAttribute(expert_kernel,
                         cudaFuncAttributeMaxDynamicSharedMemorySize, smemE);

    prep_kernel<<<32, 256>>>(hw, keys);
    routing_kernel<<<TOKENS / 8, 256>>>(x, scale);
    build_tiles_kernel<<<1, NPAT>>>();
    expert_kernel<<<MAXCHUNKS, 256, smemE>>>(x, vd, vu);
    combine_kernel<<<TOKENS, 256>>>(x, out);
}

// round 16
// speedup vs baseline: 1.0696x; 1.0696x over previous
#include <cuda_runtime.h>
#include <cuda_bf16.h>

#define TOKENS 2048
#define DDIM   1024
#define PDIM   32
#define NPAT   256
#define TOPK   4
#define NPAIRS (TOKENS * TOPK)            // 8192
#define CHUNK  32
#define MAXCHUNKS (NPAIRS / CHUNK + NPAT) // 512
#define WPAD   36     // Vd/proj row stride (floats)
#define XPAD   68     // x / Vu slice row stride (floats)
#define BUFSZ  4480   // per-stage buffer: Vd[64][36]=2304 + x[32][68]=2176
#define NBUF   4
#define PD     3
#define NSTAGE 32     // 16 A-stages + 16 B-stages (64 d each)

// ---------------- global scratch (static, allocation-free) ----------------
__device__ int   g_eidx[NPAIRS];
__device__ float g_wt[NPAIRS];
__device__ int   g_list[NPAIRS];
__device__ int   g_tiles[MAXCHUNKS];
__device__ int   g_nchunks;
__device__ float g_hwT[DDIM * PDIM];
__device__ float g_keysT[PDIM * NPAT];
__device__ unsigned int g_poutb[NPAIRS * DDIM / 2];       // bf16x2

__device__ __forceinline__ float my_silu(float z) {
    return z / (1.0f + __expf(-z));
}

__device__ __forceinline__ void mma_tf32(float& c0, float& c1, float& c2, float& c3,
                                         unsigned int a0, unsigned int a1,
                                         unsigned int a2, unsigned int a3,
                                         unsigned int b0, unsigned int b1) {
    asm volatile(
        "mma.sync.aligned.m16n8k8.row.col.f32.tf32.tf32.f32 "
        "{%0,%1,%2,%3}, {%4,%5,%6,%7}, {%8,%9}, {%0,%1,%2,%3};"
        : "+f"(c0), "+f"(c1), "+f"(c2), "+f"(c3)
        : "r"(a0), "r"(a1), "r"(a2), "r"(a3), "r"(b0), "r"(b1));
}

// tf32 m16k8 A-fragment == f16 m16k16 fragment bit-layout -> one ldmatrix.x4
__device__ __forceinline__ void ldsm_x4(unsigned int a[4], unsigned int addr) {
    asm volatile("ldmatrix.sync.aligned.m8n8.x4.shared.b16 {%0,%1,%2,%3}, [%4];"
                 : "=r"(a[0]), "=r"(a[1]), "=r"(a[2]), "=r"(a[3]) : "r"(addr));
}

__device__ __forceinline__ void cp_async16(unsigned int dst, const void* src) {
    asm volatile("cp.async.cg.shared.global [%0], [%1], 16;" :: "r"(dst), "l"(src));
}
__device__ __forceinline__ void cp_commit() {
    asm volatile("cp.async.commit_group;");
}
template<int N> __device__ __forceinline__ void cp_wait() {
    asm volatile("cp.async.wait_group %0;" :: "n"(N));
}

// ---------------- kernel 0: transpose hasher_w and keys ----------------
__global__ void prep_kernel(const float* __restrict__ hw,
                            const float* __restrict__ keys)
{
    const int tid = blockIdx.x * 256 + threadIdx.x;
    if (tid < (PDIM * DDIM) / 4) {
        const int p = tid >> 8;
        const float4 v = ((const float4*)hw)[tid];
        const int d = (tid & 255) * 4;
        g_hwT[(d + 0) * PDIM + p] = v.x;
        g_hwT[(d + 1) * PDIM + p] = v.y;
        g_hwT[(d + 2) * PDIM + p] = v.z;
        g_hwT[(d + 3) * PDIM + p] = v.w;
    }
    if (tid < (NPAT * PDIM) / 4) {
        const int n = tid >> 3;
        const int q = tid & 7;
        const float4 v = ((const float4*)keys)[tid];
        g_keysT[(q * 4 + 0) * NPAT + n] = v.x;
        g_keysT[(q * 4 + 1) * NPAT + n] = v.y;
        g_keysT[(q * 4 + 2) * NPAT + n] = v.z;
        g_keysT[(q * 4 + 3) * NPAT + n] = v.w;
    }
}

// ---------------- kernel 1: routing — 8 tokens/block, 256 blocks ----------------
__global__ __launch_bounds__(256)
void routing_kernel(const float* __restrict__ x,
                    const float* __restrict__ scale)
{
    __shared__ float wS[256 * WPAD];
    __shared__ float shh[8][PDIM];

    const int tid  = threadIdx.x;
    const int warp = tid >> 5;
    const int lane = tid & 31;
    const int tok  = blockIdx.x * 8 + warp;

    const int p4 = lane & 7;
    const int dq = lane >> 3;

    float4 acc = make_float4(0.f, 0.f, 0.f, 0.f);
    const float* xr0 = x + (size_t)tok * DDIM;

    for (int slice = 0; slice < 4; slice++) {
        __syncthreads();
        {
            const float4* src = (const float4*)(g_hwT + slice * 256 * PDIM);
            #pragma unroll
            for (int k = 0; k < 8; k++) {
                const int i = tid + k * 256;
                const int r = i >> 3, q = i & 7;
                *(float4*)&wS[r * WPAD + q * 4] = src[i];
            }
        }
        __syncthreads();

        const float* xr = xr0 + slice * 256;
        #pragma unroll 2
        for (int db = 0; db < 256; db += 16) {
            const float4 xv = *(const float4*)(xr + db + dq * 4);
            const int wb = (db + dq * 4) * WPAD + p4 * 4;
            #pragma unroll
            for (int j = 0; j < 4; j++) {
                const float4 w = *(const float4*)&wS[wb + j * WPAD];
                const float s = (j==0)?xv.x:(j==1)?xv.y:(j==2)?xv.z:xv.w;
                acc.x += s*w.x; acc.y += s*w.y; acc.z += s*w.z; acc.w += s*w.w;
            }
        }
    }

    #pragma unroll
    for (int o = 8; o <= 16; o <<= 1) {
        acc.x += __shfl_xor_sync(0xFFFFFFFFu, acc.x, o);
        acc.y += __shfl_xor_sync(0xFFFFFFFFu, acc.y, o);
        acc.z += __shfl_xor_sync(0xFFFFFFFFu, acc.z, o);
        acc.w += __shfl_xor_sync(0xFFFFFFFFu, acc.w, o);
    }
    if (dq == 0) *(float4*)&shh[warp][p4 * 4] = acc;
    __syncthreads();

    {
        const float4* src = (const float4*)g_keysT;
        #pragma unroll
        for (int k = 0; k < 8; k++)
            ((float4*)wS)[tid + k * 256] = src[tid + k * 256];
    }
    __syncthreads();

    float v[8];
    #pragma unroll
    for (int j = 0; j < 8; j++) v[j] = 0.f;
    #pragma unroll 4
    for (int p = 0; p < PDIM; p++) {
        const float hp = shh[warp][p];
        const int kb = p * NPAT + lane;
        #pragma unroll
        for (int j = 0; j < 8; j++)
            v[j] += hp * wS[kb + 32 * j];
    }

    float wv[TOPK]; int widx[TOPK];
    #pragma unroll
    for (int k = 0; k < TOPK; k++) {
        float bv = v[0]; int bj = 0;
        #pragma unroll
        for (int j = 1; j < 8; j++)
            if (v[j] > bv) { bv = v[j]; bj = j; }
        int bidx = lane + 32 * bj;
        #pragma unroll
        for (int o = 16; o; o >>= 1) {
            float ov = __shfl_xor_sync(0xFFFFFFFFu, bv, o);
            int   oi = __shfl_xor_sync(0xFFFFFFFFu, bidx, o);
            if (ov > bv || (ov == bv && oi < bidx)) { bv = ov; bidx = oi; }
        }
        wv[k] = bv; widx[k] = bidx;
        if ((bidx & 31) == lane) v[bidx >> 5] = -1e30f;
    }

    if (lane == 0) {
        float m = wv[0];
        #pragma unroll
        for (int k = 1; k < TOPK; k++) m = fmaxf(m, wv[k]);
        float e[TOPK], s = 0.0f;
        #pragma unroll
        for (int k = 0; k < TOPK; k++) { e[k] = __expf(wv[k] - m); s += e[k]; }
        const float inv = scale[0] / s;
        #pragma unroll
        for (int k = 0; k < TOPK; k++) {
            const int pair = (tok << 2) | k;
            g_eidx[pair] = widx[k];
            g_wt[pair]   = e[k] * inv;
        }
    }
}

// ---------------- kernel 2: scheduler ----------------
__global__ __launch_bounds__(NPAT, 1)
void build_tiles_kernel()
{
    __shared__ int cnt[NPAT];
    __shared__ int scn[NPAT];
    __shared__ int base[NPAT];
    __shared__ int off[NPAT];

    const int t = threadIdx.x;
    cnt[t] = 0; off[t] = 0;
    __syncthreads();

    for (int i = t; i < NPAIRS; i += NPAT)
        atomicAdd(&cnt[g_eidx[i]], 1);
    __syncthreads();

    scn[t] = cnt[t];
    __syncthreads();
    for (int o = 1; o < NPAT; o <<= 1) {
        int add = (t >= o) ? scn[t - o] : 0;
        __syncthreads();
        scn[t] += add;
        __syncthreads();
    }
    base[t] = scn[t] - cnt[t];
    __syncthreads();

    for (int i = t; i < NPAIRS; i += NPAT) {
        const int e = g_eidx[i];
        const int slot = atomicAdd(&off[e], 1);
        g_list[base[e] + slot] = i;
    }

    const int nch = (cnt[t] + CHUNK - 1) / CHUNK;
    scn[t] = nch;
    __syncthreads();
    for (int o = 1; o < NPAT; o <<= 1) {
        int add = (t >= o) ? scn[t - o] : 0;
        __syncthreads();
        scn[t] += add;
        __syncthreads();
    }
    const int cbase = scn[t] - nch;
    for (int i = 0; i < nch; i++) {
        const int start = base[t] + i * CHUNK;
        const int c     = min(CHUNK, cnt[t] - i * CHUNK);
        g_tiles[cbase + i] = (t << 19) | (start << 6) | c;
    }
    if (t == NPAT - 1) g_nchunks = scn[t];
}

// ---------------- kernel 3: fused expert — LDSM fragments + k-split phase A ----------------
// One block per chunk. 32 stages of 64 d: s<16 phase A (Vd+x), s>=16 phase B (Vu).
// Phase A warps = (mt, ks): warp covers full n=32, k-steps {ks, ks+4} per stage;
// LDSM loads A-fragments (1 instr vs 4 LDS); 4-round deterministic reduction -> projS.
__global__ __launch_bounds__(256)
void expert_kernel(const float* __restrict__ x,
                   const float* __restrict__ vd,
                   const float* __restrict__ vu)
{
    extern __shared__ float sm[];
    float* projS = sm + NBUF * BUFSZ;
    __shared__ int   spair[CHUNK];
    __shared__ float wtS[CHUNK];

    const int chunkId = blockIdx.x;
    if (chunkId >= g_nchunks) return;

    const int te    = g_tiles[chunkId];
    const int e     = te >> 19;
    const int start = (te >> 6) & 0x1FFF;
    const int cnt   = te & 0x3F;

    const int tid = threadIdx.x;
    if (tid < CHUNK) {
        const int pr = g_list[start + min(tid, cnt - 1)];
        spair[tid] = pr;
        wtS[tid]   = g_wt[pr];
    }
    __syncthreads();

    const int warp = tid >> 5;
    const int lane = tid & 31;
    const int grp  = lane >> 2;
    const int t4   = lane & 3;
    const int mt   = warp & 1;       // m-tile (tokens 16*mt..)
    const int ks   = warp >> 1;      // phase-A k-split (0..3)
    const int nt   = warp >> 1;      // phase-B col group (0..3)

    // LDSM addressing: lanes 0-7 sub0 rows, 8-15 sub1 (+8 rows), 16-23 sub2 (+4 cols), 24-31 sub3
    const int lrow = lane & 15;
    const int csh  = (lane >> 4) << 2;
    const unsigned int proj_ldsm = (unsigned int)__cvta_generic_to_shared(projS)
                                   + ((mt * 16 + lrow) * WPAD + csh) * 4;

    // unified stage issue: s<16 -> A (Vd 64x32 + x 32x64); s>=16 -> B (Vu 32x64)
    auto issue = [&](int s) {
        float* b = sm + (s & (NBUF - 1)) * BUFSZ;
        if (s < 16) {
            const unsigned int wb = (unsigned int)__cvta_generic_to_shared(b);
            const unsigned int xb = (unsigned int)__cvta_generic_to_shared(b + 2304);
            const float* wsrc = vd + ((size_t)e * DDIM + s * 64) * PDIM;
            #pragma unroll
            for (int k = 0; k < 2; k++) {
                const int i = tid + k * 256;          // 0..511
                const int r = i >> 3, q = i & 7;
                cp_async16(wb + (r * WPAD + q * 4) * 4, wsrc + r * PDIM + q * 4);
            }
            #pragma unroll
            for (int k = 0; k < 2; k++) {
                const int i = tid + k * 256;
                const int r = i >> 4, c = i & 15;
                const float* xsrc = x + (size_t)(spair[r] >> 2) * DDIM + s * 64 + c * 4;
                cp_async16(xb + (r * XPAD + c * 4) * 4, xsrc);
            }
        } else {
            const int s16 = s - 16;
            const unsigned int vb = (unsigned int)__cvta_generic_to_shared(b);
            const float* vsrc = vu + (size_t)e * PDIM * DDIM + s16 * 64;
            #pragma unroll
            for (int k = 0; k < 2; k++) {
                const int i = tid + k * 256;
                const int p = i >> 4, c = i & 15;
                cp_async16(vb + (p * XPAD + c * 4) * 4, vsrc + p * DDIM + c * 4);
            }
        }
    };

    // phase-A accumulators: full n=32 per warp (k-partial): c[n-tile][4]
    float c[4][4];
    #pragma unroll
    for (int i = 0; i < 4; i++)
        #pragma unroll
        for (int j = 0; j < 4; j++) c[i][j] = 0.f;

    #pragma unroll
    for (int s = 0; s < PD; s++) { issue(s); cp_commit(); }

    for (int s = 0; s < NSTAGE; s++) {
        if (s < NSTAGE - PD) { issue(s + PD); cp_commit(); cp_wait<PD>(); }
        else if (s == NSTAGE - PD)     cp_wait<PD - 1>();
        else if (s == NSTAGE - PD + 1) cp_wait<PD - 2>();
        else                           cp_wait<0>();
        __syncthreads();

        float* b = sm + (s & (NBUF - 1)) * BUFSZ;

        if (s < 16) {
            // ---- phase A: warp covers k-steps {ks, ks+4}, all 4 n-tiles ----
            const unsigned int xaddr = (unsigned int)__cvta_generic_to_shared(b + 2304)
                                       + ((mt * 16 + lrow) * XPAD + csh) * 4;
            #pragma unroll
            for (int jj = 0; jj < 2; jj++) {
                const int kb = (ks + jj * 4) * 8;
                unsigned int a[4];
                ldsm_x4(a, xaddr + kb * 4);
                #pragma unroll
                for (int n2 = 0; n2 < 4; n2++) {
                    const unsigned int b0 = __float_as_uint(b[(kb + t4) * WPAD + n2 * 8 + grp]);
                    const unsigned int b1 = __float_as_uint(b[(kb + t4 + 4) * WPAD + n2 * 8 + grp]);
                    mma_tf32(c[n2][0], c[n2][1], c[n2][2], c[n2][3],
                             a[0], a[1], a[2], a[3], b0, b1);
                }
            }
        } else {
            if (s == 16) {
                // deterministic 4-round k-reduction into projS; silu+wt fused in last round
                const int row0 = mt * 16 + grp;
                const float w0 = wtS[row0], w1 = wtS[row0 + 8];
                #pragma unroll
                for (int r = 0; r < 4; r++) {
                    if (ks == r) {
                        #pragma unroll
                        for (int n2 = 0; n2 < 4; n2++) {
                            const int bse = row0 * WPAD + n2 * 8 + t4 * 2;
                            if (r == 0) {
                                projS[bse]              = c[n2][0];
                                projS[bse + 1]          = c[n2][1];
                                projS[bse + 8 * WPAD]     = c[n2][2];
                                projS[bse + 8 * WPAD + 1] = c[n2][3];
                            } else if (r < 3) {
                                projS[bse]              += c[n2][0];
                                projS[bse + 1]          += c[n2][1];
                                projS[bse + 8 * WPAD]     += c[n2][2];
                                projS[bse + 8 * WPAD + 1] += c[n2][3];
                            } else {
                                projS[bse]              = w0 * my_silu(projS[bse]              + c[n2][0]);
                                projS[bse + 1]          = w0 * my_silu(projS[bse + 1]          + c[n2][1]);
                                projS[bse + 8 * WPAD]     = w1 * my_silu(projS[bse + 8 * WPAD]     + c[n2][2]);
                                projS[bse + 8 * WPAD + 1] = w1 * my_silu(projS[bse + 8 * WPAD + 1] + c[n2][3]);
                            }
                        }
                    }
                    __syncthreads();
                }
            }

            // ---- phase B: 64-d slice, warp = (mt, 16-col group), LDSM for proj frags ----
            const int s16 = s - 16;
            const int nb0 = nt * 16;
            float d0[4] = {0.f,0.f,0.f,0.f};
            float d1[4] = {0.f,0.f,0.f,0.f};
            #pragma unroll
            for (int kk = 0; kk < 4; kk++) {
                const int kb = kk * 8;
                unsigned int a[4];
                ldsm_x4(a, proj_ldsm + kb * 4);
                {
                    const unsigned int b0 = __float_as_uint(b[(kb + t4) * XPAD + nb0 + grp]);
                    const unsigned int b1 = __float_as_uint(b[(kb + t4 + 4) * XPAD + nb0 + grp]);
                    mma_tf32(d0[0], d0[1], d0[2], d0[3], a[0], a[1], a[2], a[3], b0, b1);
                }
                {
                    const unsigned int b0 = __float_as_uint(b[(kb + t4) * XPAD + nb0 + 8 + grp]);
                    const unsigned int b1 = __float_as_uint(b[(kb + t4 + 4) * XPAD + nb0 + 8 + grp]);
                    mma_tf32(d1[0], d1[1], d1[2], d1[3], a[0], a[1], a[2], a[3], b0, b1);
                }
            }

            const int tok0 = mt * 16 + grp;
            const int tok1 = tok0 + 8;
            const int colb = s16 * 64 + nb0 + t4 * 2;
            if (tok0 < cnt) {
                __nv_bfloat162 v0 = __floats2bfloat162_rn(d0[0], d0[1]);
                __nv_bfloat162 v1 = __floats2bfloat162_rn(d1[0], d1[1]);
                const int rb = spair[tok0] * DDIM;
                g_poutb[(rb + colb) >> 1]     = *(unsigned int*)&v0;
                g_poutb[(rb + colb + 8) >> 1] = *(unsigned int*)&v1;
            }
            if (tok1 < cnt) {
                __nv_bfloat162 v0 = __floats2bfloat162_rn(d0[2], d0[3]);
                __nv_bfloat162 v1 = __floats2bfloat162_rn(d1[2], d1[3]);
                const int rb = spair[tok1] * DDIM;
                g_poutb[(rb + colb) >> 1]     = *(unsigned int*)&v0;
                g_poutb[(rb + colb + 8) >> 1] = *(unsigned int*)&v1;
            }
        }
        __syncthreads();
    }
}

// ---------------- kernel 4: combine ----------------
__global__ __launch_bounds__(256)
void combine_kernel(const float* __restrict__ x, float* __restrict__ out)
{
    const int tok = blockIdx.x;
    const int t   = threadIdx.x;
    float4 o = ((const float4*)(x + (size_t)tok * DDIM))[t];
    #pragma unroll
    for (int k = 0; k < TOPK; k++) {
        const uint2 u = *(const uint2*)&g_poutb[((tok << 2) | k) * (DDIM / 2) + t * 2];
        const __nv_bfloat162 lo = *(const __nv_bfloat162*)&u.x;
        const __nv_bfloat162 hi = *(const __nv_bfloat162*)&u.y;
        const float2 flo = __bfloat1622float2(lo);
        const float2 fhi = __bfloat1622float2(hi);
        o.x += flo.x; o.y += flo.y; o.z += fhi.x; o.w += fhi.y;
    }
    ((float4*)(out + (size_t)tok * DDIM))[t] = o;
}

// ---------------- launch ----------------
extern "C" void kernel_launch(void* const* d_in, const int* in_sizes, int n_in,
                              void* d_out, int out_size) {
    const float* x     = (const float*)d_in[0];
    const float* hw    = (const float*)d_in[1];
    const float* keys  = (const float*)d_in[2];
    const float* vd    = (const float*)d_in[3];
    const float* vu    = (const float*)d_in[4];
    const float* scale = (const float*)d_in[5];
    float* out = (float*)d_out;

    const int smemE = (NBUF * BUFSZ + CHUNK * WPAD) * (int)sizeof(float);  // 76288 B
    cudaFuncSetAttribute(expert_kernel,
                         cudaFuncAttributeMaxDynamicSharedMemorySize, smemE);

    prep_kernel<<<32, 256>>>(hw, keys);
    routing_kernel<<<TOKENS / 8, 256>>>(x, scale);
    build_tiles_kernel<<<1, NPAT>>>();
    expert_kernel<<<MAXCHUNKS, 256, smemE>>>(x, vd, vu);
    combine_kernel<<<TOKENS, 256>>>(x, out);
}